// round 4
// baseline (speedup 1.0000x reference)
#include <cuda_runtime.h>
#include <cstdint>

// Problem constants
#define TOKENS (8 * 4096)   // 32768 rows
#define HID 768
#define INT 3072
#define NTAGS 64

// ---------------------------------------------------------------------------
// Scratch (static device memory — allocation-free per harness rules)
// ---------------------------------------------------------------------------
__device__ __align__(256) float g_x[(size_t)TOKENS * HID];    // LN1 output (tf32-rounded)
__device__ __align__(256) float g_ffx[(size_t)TOKENS * HID];  // ff + x (LN2 input)
__device__ __align__(256) float g_h[(size_t)TOKENS * INT];    // relu(x@W1+b1) (tf32-rounded)
__device__ __align__(256) float g_w1r[HID * INT];             // tf32-rounded W1
__device__ __align__(256) float g_w2r[INT * HID];             // tf32-rounded W2
__device__ __align__(256) float g_tmp[NTAGS * HID];           // tag_emb@Wv+bv
__device__ __align__(256) float g_ptag[NTAGS * HID];          // per-tag vector

// ---------------------------------------------------------------------------
// Helpers
// ---------------------------------------------------------------------------
__device__ __forceinline__ float tf32r(float x) {
    uint32_t u;
    asm("cvt.rna.tf32.f32 %0, %1;" : "=r"(u) : "f"(x));
    return __uint_as_float(u);
}

__device__ __forceinline__ void cp_async16(uint32_t saddr, const void* gaddr) {
    asm volatile("cp.async.cg.shared.global [%0], [%1], 16;" :: "r"(saddr), "l"(gaddr));
}
__device__ __forceinline__ void cp_commit() { asm volatile("cp.async.commit_group;"); }
__device__ __forceinline__ void cp_wait0()  { asm volatile("cp.async.wait_group 0;"); }

__device__ __forceinline__ void mma_tf32(float c[4], const uint32_t a[4], const uint32_t b[2]) {
    asm volatile(
        "mma.sync.aligned.m16n8k8.row.col.f32.tf32.tf32.f32 "
        "{%0,%1,%2,%3}, {%4,%5,%6,%7}, {%8,%9}, {%0,%1,%2,%3};"
        : "+f"(c[0]), "+f"(c[1]), "+f"(c[2]), "+f"(c[3])
        : "r"(a[0]), "r"(a[1]), "r"(a[2]), "r"(a[3]), "r"(b[0]), "r"(b[1]));
}

// ---------------------------------------------------------------------------
// Weight rounding: g_w{1,2}r = round_rna_tf32(W)
// ---------------------------------------------------------------------------
template<int W>
__global__ void round_w_kernel(const float* __restrict__ in) {
    float* out = W ? g_w2r : g_w1r;
    int i = blockIdx.x * blockDim.x + threadIdx.x;
    const int n = HID * INT;
    if (i < n) out[i] = tf32r(in[i]);
}

// ---------------------------------------------------------------------------
// per-tag precompute: O[t][n] = sum_k E[t][k] * W[k][n] + bias[n]
// STAGE 0: E = tag_emb (param), O = g_tmp.  STAGE 1: E = g_tmp, O = g_ptag.
// ---------------------------------------------------------------------------
template<int STAGE>
__global__ void __launch_bounds__(256)
tag_gemm_kernel(const float* __restrict__ Eparam, const float* __restrict__ W,
                const float* __restrict__ bias) {
    __shared__ float se[HID];
    const float* E = STAGE ? g_tmp : Eparam;
    float* O = STAGE ? g_ptag : g_tmp;
    int t = blockIdx.x;
    for (int c = threadIdx.x; c < HID; c += 256) se[c] = E[t * HID + c];
    __syncthreads();
    int n0 = threadIdx.x, n1 = n0 + 256, n2 = n0 + 512;
    float a0 = bias[n0], a1 = bias[n1], a2 = bias[n2];
    for (int k = 0; k < HID; k += 4) {
#pragma unroll
        for (int u = 0; u < 4; u++) {
            float e = se[k + u];
            const float* w = W + (long)(k + u) * HID;
            a0 = fmaf(e, w[n0], a0);
            a1 = fmaf(e, w[n1], a1);
            a2 = fmaf(e, w[n2], a2);
        }
    }
    O[t * HID + n0] = a0;
    O[t * HID + n1] = a1;
    O[t * HID + n2] = a2;
}

// ---------------------------------------------------------------------------
// Block reduce for (sum, sumsq) over 256 threads
// ---------------------------------------------------------------------------
__device__ __forceinline__ void block_reduce2(float& s, float& s2, float* red) {
#pragma unroll
    for (int o = 16; o > 0; o >>= 1) {
        s  += __shfl_xor_sync(0xffffffffu, s,  o);
        s2 += __shfl_xor_sync(0xffffffffu, s2, o);
    }
    int warp = threadIdx.x >> 5, lane = threadIdx.x & 31;
    if (lane == 0) { red[warp] = s; red[8 + warp] = s2; }
    __syncthreads();
    if (warp == 0) {
        float a  = (lane < 8) ? red[lane] : 0.f;
        float a2 = (lane < 8) ? red[8 + lane] : 0.f;
#pragma unroll
        for (int o = 4; o > 0; o >>= 1) {
            a  += __shfl_xor_sync(0xffffffffu, a,  o);
            a2 += __shfl_xor_sync(0xffffffffu, a2, o);
        }
        if (lane == 0) { red[16] = a; red[17] = a2; }
    }
    __syncthreads();
    s = red[16]; s2 = red[17];
}

// ---------------------------------------------------------------------------
// LN1: g_x = tf32r( LN( we + per_tag[tag]*mask ) * g + b )
// ---------------------------------------------------------------------------
__global__ void __launch_bounds__(256)
ln1_kernel(const float* __restrict__ we, const int* __restrict__ tags,
           const int* __restrict__ mask,
           const float* __restrict__ g, const float* __restrict__ b) {
    __shared__ float red[18];
    long row = blockIdx.x;
    const float* wr = we + row * HID;
    const float* pr = g_ptag + (long)tags[row] * HID;
    float mk = (float)mask[row];
    int t = threadIdx.x;
    float v[3]; float s = 0.f, s2 = 0.f;
#pragma unroll
    for (int j = 0; j < 3; j++) {
        int c = t + j * 256;
        float val = wr[c] + pr[c] * mk;
        v[j] = val; s += val; s2 += val * val;
    }
    block_reduce2(s, s2, red);
    float mu = s * (1.f / 768.f);
    float var = s2 * (1.f / 768.f) - mu * mu;
    float rs = rsqrtf(var + 1e-12f);
#pragma unroll
    for (int j = 0; j < 3; j++) {
        int c = t + j * 256;
        g_x[row * HID + c] = tf32r((v[j] - mu) * rs * g[c] + b[c]);
    }
}

// ---------------------------------------------------------------------------
// LN2: out = LN(g_ffx) * g + b
// ---------------------------------------------------------------------------
__global__ void __launch_bounds__(256)
ln2_kernel(const float* __restrict__ g, const float* __restrict__ b,
           float* __restrict__ out) {
    __shared__ float red[18];
    long row = blockIdx.x;
    const float* in = g_ffx + row * HID;
    int t = threadIdx.x;
    float v[3]; float s = 0.f, s2 = 0.f;
#pragma unroll
    for (int j = 0; j < 3; j++) {
        int c = t + j * 256;
        float val = in[c];
        v[j] = val; s += val; s2 += val * val;
    }
    block_reduce2(s, s2, red);
    float mu = s * (1.f / 768.f);
    float var = s2 * (1.f / 768.f) - mu * mu;
    float rs = rsqrtf(var + 1e-12f);
#pragma unroll
    for (int j = 0; j < 3; j++) {
        int c = t + j * 256;
        out[row * HID + c] = (v[j] - mu) * rs * g[c] + b[c];
    }
}

// ---------------------------------------------------------------------------
// tf32 GEMM: C[M,N] = A[M,K] @ B[K,N]  (+ epilogue)
//   MODE 0: A=g_x,  B=g_w1r, C=g_h,   epi = tf32r(relu(acc + bias))
//   MODE 1: A=g_h,  B=g_w2r, C=g_ffx, epi = acc + bias + g_x (residual)
// 128x128x16 block tile, 8 warps of 64x32, cp.async double buffer.
// A smem: per-row BK=16 floats, 16B chunks XOR-swizzled by ((m>>1)&3).
// B smem: [BK][BN+8] padded rows.
// ---------------------------------------------------------------------------
template<int MODE, int N, int K>
__global__ void __launch_bounds__(256, 2)
gemm_kernel(const float* __restrict__ bias) {
    constexpr int BM = 128, BN = 128, BK = 16;
    constexpr int BSTR = BN + 8;  // 136 floats: conflict-free B frags, 16B-aligned rows
    __shared__ float sA[2][BM * BK];
    __shared__ float sB[2][BK * BSTR];

    const float* A = (MODE == 0) ? g_x : g_h;
    const float* B = (MODE == 0) ? g_w1r : g_w2r;
    float* C       = (MODE == 0) ? g_h : g_ffx;

    const int tid = threadIdx.x;
    const int lane = tid & 31;
    const int warp = tid >> 5;
    const int wr = (warp & 1) * 64;   // warp row in tile
    const int wc = (warp >> 1) * 32;  // warp col in tile
    const long blockRow = (long)blockIdx.y * BM;
    const int blockCol = blockIdx.x * BN;

    float acc[4][4][4];
#pragma unroll
    for (int mi = 0; mi < 4; mi++)
#pragma unroll
        for (int ni = 0; ni < 4; ni++)
#pragma unroll
            for (int r = 0; r < 4; r++) acc[mi][ni][r] = 0.f;

    const uint32_t sA0 = (uint32_t)__cvta_generic_to_shared(&sA[0][0]);
    const uint32_t sB0 = (uint32_t)__cvta_generic_to_shared(&sB[0][0]);

    auto load_tile = [&](int kt, int st) {
#pragma unroll
        for (int i = 0; i < 2; i++) {
            int m = (tid >> 2) + i * 64;
            int c = tid & 3;
            const float* gp = A + (blockRow + m) * (long)K + kt * BK + c * 4;
            uint32_t so = (uint32_t)(m * BK + ((c ^ ((m >> 1) & 3)) << 2));
            cp_async16(sA0 + (uint32_t)st * (BM * BK * 4) + so * 4, gp);
        }
#pragma unroll
        for (int i = 0; i < 2; i++) {
            int idx = tid + i * 256;
            int kk = idx >> 5, cn = idx & 31;
            const float* gp = B + (long)(kt * BK + kk) * N + blockCol + cn * 4;
            uint32_t so = (uint32_t)(kk * BSTR + cn * 4);
            cp_async16(sB0 + (uint32_t)st * (BK * BSTR * 4) + so * 4, gp);
        }
        cp_commit();
    };

    auto compute_tile = [&](int st) {
        const float* a = &sA[st][0];
        const float* bb = &sB[st][0];
#pragma unroll
        for (int ks = 0; ks < 2; ks++) {
            const int kk = ks * 8;
            uint32_t af[4][4], bf[4][2];
#pragma unroll
            for (int mi = 0; mi < 4; mi++) {
                int m0 = wr + mi * 16 + (lane >> 2);
                int swz = (m0 >> 1) & 3;
                int base = m0 * BK + (lane & 3);
                int c0 = ((kk >> 2) ^ swz) << 2;
                int c1 = (((kk >> 2) + 1) ^ swz) << 2;
                af[mi][0] = __float_as_uint(a[base + c0]);
                af[mi][1] = __float_as_uint(a[base + c0 + 8 * BK]);
                af[mi][2] = __float_as_uint(a[base + c1]);
                af[mi][3] = __float_as_uint(a[base + c1 + 8 * BK]);
            }
#pragma unroll
            for (int ni = 0; ni < 4; ni++) {
                int off = (kk + (lane & 3)) * BSTR + wc + ni * 8 + (lane >> 2);
                bf[ni][0] = __float_as_uint(bb[off]);
                bf[ni][1] = __float_as_uint(bb[off + 4 * BSTR]);
            }
#pragma unroll
            for (int mi = 0; mi < 4; mi++)
#pragma unroll
                for (int ni = 0; ni < 4; ni++)
                    mma_tf32(acc[mi][ni], af[mi], bf[ni]);
        }
    };

    const int kTiles = K / BK;
    load_tile(0, 0);
    for (int t = 0; t < kTiles; t++) {
        cp_wait0();
        __syncthreads();
        if (t + 1 < kTiles) load_tile(t + 1, (t + 1) & 1);
        compute_tile(t & 1);
    }

    // Epilogue
#pragma unroll
    for (int mi = 0; mi < 4; mi++) {
#pragma unroll
        for (int ri = 0; ri < 2; ri++) {
            long row = blockRow + wr + mi * 16 + (lane >> 2) + ri * 8;
#pragma unroll
            for (int ni = 0; ni < 4; ni++) {
                int col = blockCol + wc + ni * 8 + (lane & 3) * 2;
                float v0 = acc[mi][ni][ri * 2 + 0] + bias[col];
                float v1 = acc[mi][ni][ri * 2 + 1] + bias[col + 1];
                if (MODE == 0) {
                    v0 = tf32r(fmaxf(v0, 0.f));
                    v1 = tf32r(fmaxf(v1, 0.f));
                } else {
                    const float2 r2 = *(const float2*)(g_x + row * N + col);
                    v0 += r2.x; v1 += r2.y;
                }
                float2 o; o.x = v0; o.y = v1;
                *(float2*)(C + row * (long)N + col) = o;
            }
        }
    }
}

// ---------------------------------------------------------------------------
// Launch
// ---------------------------------------------------------------------------
extern "C" void kernel_launch(void* const* d_in, const int* in_sizes, int n_in,
                              void* d_out, int out_size) {
    const float* we      = (const float*)d_in[0];
    const int*   tags    = (const int*)d_in[1];
    const int*   mask    = (const int*)d_in[2];
    const float* tag_emb = (const float*)d_in[3];
    const float* Wv      = (const float*)d_in[4];
    const float* bv      = (const float*)d_in[5];
    const float* Wo      = (const float*)d_in[6];
    const float* bo      = (const float*)d_in[7];
    const float* ln1g    = (const float*)d_in[8];
    const float* ln1b    = (const float*)d_in[9];
    const float* W1      = (const float*)d_in[10];
    const float* b1      = (const float*)d_in[11];
    const float* W2      = (const float*)d_in[12];
    const float* b2      = (const float*)d_in[13];
    const float* ln2g    = (const float*)d_in[14];
    const float* ln2b    = (const float*)d_in[15];
    float* out = (float*)d_out;

    const int nw = HID * INT;
    round_w_kernel<0><<<(nw + 255) / 256, 256>>>(W1);
    round_w_kernel<1><<<(nw + 255) / 256, 256>>>(W2);

    tag_gemm_kernel<0><<<NTAGS, 256>>>(tag_emb, Wv, bv);
    tag_gemm_kernel<1><<<NTAGS, 256>>>(nullptr, Wo, bo);

    ln1_kernel<<<TOKENS, 256>>>(we, tags, mask, ln1g, ln1b);

    // GEMM1: [32768,768] @ [768,3072], relu+bias, tf32-rounded store
    gemm_kernel<0, INT, HID><<<dim3(INT / 128, TOKENS / 128), 256>>>(b1);

    // GEMM2: [32768,3072] @ [3072,768], bias + residual(g_x)
    gemm_kernel<1, HID, INT><<<dim3(HID / 128, TOKENS / 128), 256>>>(b2);

    ln2_kernel<<<TOKENS, 256>>>(ln2g, ln2b, out);
}